// round 1
// baseline (speedup 1.0000x reference)
#include <cuda_runtime.h>
#include <math.h>

#define NB 16
#define NT 100
#define H0 159
#define NW 132
#define HID 100
#define FEAT 17424   /* 132*132 */

// ---------------- static scratch (no runtime allocation allowed) ----------
__device__ float g_xT[(size_t)NB * NW * NT * 159];   // [b][w][i][h]
__device__ float g_c1[(size_t)NB * NW * NT * 150];
__device__ float g_c2[(size_t)NB * NW * NT * 141];
__device__ float g_c3[(size_t)NB * NW * NT * 132];
__device__ float g_gi[(size_t)NB * NT * FEAT];       // [b][t][feat]
__device__ float g_wt1[10 * 100 * 100];              // [k][i][o]
__device__ float g_wt2[10 * 100 * 100];
__device__ float g_wt3[10 * 100 * 100];
__device__ float g_xw[(size_t)NB * NT * 300];        // GRU input proj (no bias)
__device__ float g_h [(size_t)NB * NT * HID];        // GRU outputs

// ---------------- weight transpose [o][i][k] -> [k][i][o] -----------------
__global__ void wtrans_k(const float* __restrict__ w1,
                         const float* __restrict__ w2,
                         const float* __restrict__ w3)
{
    int idx = blockIdx.x * blockDim.x + threadIdx.x;
    if (idx >= 100 * 100 * 10) return;
    int o = idx / 1000;
    int i = (idx / 10) % 100;
    int k = idx % 10;
    int dst = (k * 100 + i) * 100 + o;
    g_wt1[dst] = w1[idx];
    g_wt2[dst] = w2[idx];
    g_wt3[dst] = w3[idx];
}

// ---------------- x: [b][i][h][w] -> [b][w][i][h] --------------------------
__global__ void transpose_x_k(const float* __restrict__ x)
{
    __shared__ float s[32][33];
    int plane = blockIdx.x;               // b*100 + i
    int b = plane / 100, i = plane % 100;
    int h0 = blockIdx.y * 32, w0 = blockIdx.z * 32;
    int tx = threadIdx.x, ty = threadIdx.y;
    const float* xp = x + (size_t)plane * (159 * 132);
#pragma unroll
    for (int j = 0; j < 4; j++) {
        int h = h0 + ty + j * 8, w = w0 + tx;
        if (h < 159 && w < 132) s[ty + j * 8][tx] = xp[h * 132 + w];
    }
    __syncthreads();
#pragma unroll
    for (int j = 0; j < 4; j++) {
        int w = w0 + ty + j * 8, h = h0 + tx;
        if (w < 132 && h < 159)
            g_xT[((size_t)(b * 132 + w) * 100 + i) * 159 + h] = s[tx][ty + j * 8];
    }
}

// ---------------- conv along h, full channel mix ---------------------------
// in : [b][w][i][HIN_]  (one (b,w) slab per block, in shared memory)
// wt : [k][i][o]        (float4 per 4 o's, L2 resident)
// out: [b][w][o][HOUT_]
template<int HIN_, int HOUT_, int TH_>
__global__ void __launch_bounds__(256, 2)
conv_k(const float* __restrict__ in, const float* __restrict__ wt,
       const float* __restrict__ bias, float* __restrict__ out)
{
    extern __shared__ float xs[];        // 100*HIN_ + 64 pad
    const int bw = blockIdx.x;           // b*132 + w
    const float* inp = in + (size_t)bw * (100 * HIN_);
    float* outp = out + (size_t)bw * (100 * HOUT_);
    const int tid = threadIdx.x;

    for (int idx = tid; idx < 100 * HIN_; idx += 256) xs[idx] = inp[idx];
    __syncthreads();

    const int og = tid % 25;             // 25 groups of 4 output channels
    const int hg = tid / 25;             // 10 h-groups of TH_ outputs
    if (hg >= 10) return;
    const int h0 = hg * TH_;
    const int ob = og * 4;

    float acc0[TH_], acc1[TH_], acc2[TH_], acc3[TH_];
#pragma unroll
    for (int hh = 0; hh < TH_; hh++) { acc0[hh] = 0.f; acc1[hh] = 0.f; acc2[hh] = 0.f; acc3[hh] = 0.f; }

    for (int i = 0; i < 100; i++) {
        float xr[TH_ + 9];
#pragma unroll
        for (int j = 0; j < TH_ + 9; j++) xr[j] = xs[i * HIN_ + h0 + j];
        const float4* wrow = (const float4*)(wt + i * 100 + ob);
#pragma unroll
        for (int k = 0; k < 10; k++) {
            float4 wv = wrow[k * 2500];   // (k*100+i)*100 + ob, as float4 index
#pragma unroll
            for (int hh = 0; hh < TH_; hh++) {
                float xv = xr[hh + k];
                acc0[hh] += wv.x * xv;
                acc1[hh] += wv.y * xv;
                acc2[hh] += wv.z * xv;
                acc3[hh] += wv.w * xv;
            }
        }
    }
    float b0 = bias[ob], b1 = bias[ob + 1], b2 = bias[ob + 2], b3 = bias[ob + 3];
#pragma unroll
    for (int hh = 0; hh < TH_; hh++) {
        int h = h0 + hh;
        if (h < HOUT_) {
            outp[(ob + 0) * HOUT_ + h] = acc0[hh] + b0;
            outp[(ob + 1) * HOUT_ + h] = acc1[hh] + b1;
            outp[(ob + 2) * HOUT_ + h] = acc2[hh] + b2;
            outp[(ob + 3) * HOUT_ + h] = acc3[hh] + b3;
        }
    }
}

// ---------------- c3: [b][w][t][h] -> gi [b][t][h*132+w] -------------------
__global__ void transpose_c_k()
{
    __shared__ float s[32][33];
    int plane = blockIdx.x;               // b*100 + t
    int b = plane / 100, t = plane % 100;
    int h0 = blockIdx.y * 32, w0 = blockIdx.z * 32;
    int tx = threadIdx.x, ty = threadIdx.y;
#pragma unroll
    for (int j = 0; j < 4; j++) {
        int w = w0 + ty + j * 8, h = h0 + tx;
        if (w < 132 && h < 132)
            s[ty + j * 8][tx] = g_c3[((size_t)(b * 132 + w) * 100 + t) * 132 + h];
    }
    __syncthreads();
#pragma unroll
    for (int j = 0; j < 4; j++) {
        int h = h0 + ty + j * 8, w = w0 + tx;
        if (h < 132 && w < 132)
            g_gi[(size_t)plane * FEAT + h * 132 + w] = s[tx][ty + j * 8];
    }
}

// ---------------- GRU input projection: xw = gi @ w_ih^T -------------------
// C[1600,300] = A[1600,17424] * B[300,17424]^T     (TN, K-major both sides)
__global__ void gemm_xw_k(const float* __restrict__ Bm)
{
    __shared__ float As[16][64];
    __shared__ float Bs[16][64];
    const int m0 = blockIdx.x * 64, n0 = blockIdx.y * 64;
    const int tid = threadIdx.x;
    const int tx = tid & 15, ty = tid >> 4;
    const int lrow = tid >> 2, lk = (tid & 3) << 2;

    float acc[4][4];
#pragma unroll
    for (int a = 0; a < 4; a++)
#pragma unroll
        for (int c = 0; c < 4; c++) acc[a][c] = 0.f;

    const float* aptr = g_gi + (size_t)(m0 + lrow) * FEAT + lk;
    const int nn = n0 + lrow;
    const float* bptr = Bm + (size_t)(nn < 300 ? nn : 0) * FEAT + lk;

    for (int k0 = 0; k0 < FEAT; k0 += 16) {
        float4 av = *(const float4*)(aptr + k0);
        float4 bv = make_float4(0.f, 0.f, 0.f, 0.f);
        if (nn < 300) bv = *(const float4*)(bptr + k0);
        __syncthreads();
        As[lk + 0][lrow] = av.x; As[lk + 1][lrow] = av.y;
        As[lk + 2][lrow] = av.z; As[lk + 3][lrow] = av.w;
        Bs[lk + 0][lrow] = bv.x; Bs[lk + 1][lrow] = bv.y;
        Bs[lk + 2][lrow] = bv.z; Bs[lk + 3][lrow] = bv.w;
        __syncthreads();
#pragma unroll
        for (int kk = 0; kk < 16; kk++) {
            float4 a = *(const float4*)&As[kk][ty << 2];
            float4 b = *(const float4*)&Bs[kk][tx << 2];
            acc[0][0] += a.x * b.x; acc[0][1] += a.x * b.y; acc[0][2] += a.x * b.z; acc[0][3] += a.x * b.w;
            acc[1][0] += a.y * b.x; acc[1][1] += a.y * b.y; acc[1][2] += a.y * b.z; acc[1][3] += a.y * b.w;
            acc[2][0] += a.z * b.x; acc[2][1] += a.z * b.y; acc[2][2] += a.z * b.z; acc[2][3] += a.z * b.w;
            acc[3][0] += a.w * b.x; acc[3][1] += a.w * b.y; acc[3][2] += a.w * b.z; acc[3][3] += a.w * b.w;
        }
    }
#pragma unroll
    for (int ii = 0; ii < 4; ii++) {
        int m = m0 + (ty << 2) + ii;
#pragma unroll
        for (int jj = 0; jj < 4; jj++) {
            int n = n0 + (tx << 2) + jj;
            if (n < 300) g_xw[(size_t)m * 300 + n] = acc[ii][jj];
        }
    }
}

// ---------------- GRU recurrence: one block per batch element --------------
__global__ void __launch_bounds__(320)
gru_k(const float* __restrict__ w_hh, const float* __restrict__ b_ih,
      const float* __restrict__ b_hh)
{
    const int b = blockIdx.x;
    const int g = threadIdx.x;           // 0..319, 300 gate rows active
    __shared__ float h_s[104];
    __shared__ float gh_s[300];
    __shared__ float xw_s[300];

    float wreg[100];
    float bih = 0.f, bhh = 0.f;
    if (g < 300) {
        bih = b_ih[g];
        bhh = b_hh[g];
#pragma unroll
        for (int j = 0; j < 100; j++) wreg[j] = w_hh[g * 100 + j];
    }
    if (g < 104) h_s[g] = 0.f;
    __syncthreads();

    const float* xwp = g_xw + (size_t)b * 100 * 300;
    for (int t = 0; t < 100; t++) {
        if (g < 300) {
            float xv = xwp[t * 300 + g] + bih;
            float acc = bhh;
#pragma unroll
            for (int j4 = 0; j4 < 25; j4++) {
                float4 hv = *(const float4*)&h_s[j4 * 4];
                acc += wreg[j4 * 4 + 0] * hv.x;
                acc += wreg[j4 * 4 + 1] * hv.y;
                acc += wreg[j4 * 4 + 2] * hv.z;
                acc += wreg[j4 * 4 + 3] * hv.w;
            }
            gh_s[g] = acc;
            xw_s[g] = xv;
        }
        __syncthreads();
        if (g < 100) {
            float r = 1.f / (1.f + expf(-(xw_s[g] + gh_s[g])));
            float z = 1.f / (1.f + expf(-(xw_s[100 + g] + gh_s[100 + g])));
            float n = tanhf(xw_s[200 + g] + r * gh_s[200 + g]);
            float hn = (1.f - z) * n + z * h_s[g];
            h_s[g] = hn;
            g_h[((size_t)b * 100 + t) * 100 + g] = hn;
        }
        __syncthreads();
    }
}

// ---------------- output heads ---------------------------------------------
__global__ void heads_k(const float* __restrict__ wy1, const float* __restrict__ by1,
                        const float* __restrict__ wy2, const float* __restrict__ by2,
                        float* __restrict__ out)
{
    int idx = blockIdx.x * blockDim.x + threadIdx.x;
    if (idx >= 1600 * 17) return;
    int bt = idx / 17, c = idx - bt * 17;
    const float* gv = g_h + (size_t)bt * 100;
    if (c < 14) {
        const float* wv = wy1 + c * 100;
        float acc = by1[c];
#pragma unroll 4
        for (int j = 0; j < 100; j++) acc += gv[j] * wv[j];
        out[bt * 14 + c] = 1.f / (1.f + expf(-acc));
    } else {
        int c2 = c - 14;
        const float* wv = wy2 + c2 * 100;
        float acc = by2[c2];
#pragma unroll 4
        for (int j = 0; j < 100; j++) acc += gv[j] * wv[j];
        out[1600 * 14 + bt * 3 + c2] = tanhf(acc) * 10.f;
    }
}

// ---------------- launch ----------------------------------------------------
extern "C" void kernel_launch(void* const* d_in, const int* in_sizes, int n_in,
                              void* d_out, int out_size)
{
    (void)in_sizes; (void)n_in; (void)out_size;
    const float* x    = (const float*)d_in[0];
    const float* w1   = (const float*)d_in[1];
    const float* bc1  = (const float*)d_in[2];
    const float* w2   = (const float*)d_in[3];
    const float* bc2  = (const float*)d_in[4];
    const float* w3   = (const float*)d_in[5];
    const float* bc3  = (const float*)d_in[6];
    const float* w_ih = (const float*)d_in[7];
    const float* w_hh = (const float*)d_in[8];
    const float* b_ih = (const float*)d_in[9];
    const float* b_hh = (const float*)d_in[10];
    const float* w_y1 = (const float*)d_in[11];
    const float* b_y1 = (const float*)d_in[12];
    const float* w_y2 = (const float*)d_in[13];
    const float* b_y2 = (const float*)d_in[14];
    float* out = (float*)d_out;

    void *pxT, *pc1, *pc2, *pc3, *pw1, *pw2, *pw3;
    cudaGetSymbolAddress(&pxT, g_xT);
    cudaGetSymbolAddress(&pc1, g_c1);
    cudaGetSymbolAddress(&pc2, g_c2);
    cudaGetSymbolAddress(&pc3, g_c3);
    cudaGetSymbolAddress(&pw1, g_wt1);
    cudaGetSymbolAddress(&pw2, g_wt2);
    cudaGetSymbolAddress(&pw3, g_wt3);

    cudaFuncSetAttribute(conv_k<159, 150, 15>, cudaFuncAttributeMaxDynamicSharedMemorySize, (100 * 159 + 64) * 4);
    cudaFuncSetAttribute(conv_k<150, 141, 15>, cudaFuncAttributeMaxDynamicSharedMemorySize, (100 * 150 + 64) * 4);
    cudaFuncSetAttribute(conv_k<141, 132, 14>, cudaFuncAttributeMaxDynamicSharedMemorySize, (100 * 141 + 64) * 4);

    wtrans_k<<<(100 * 100 * 10 + 255) / 256, 256>>>(w1, w2, w3);
    transpose_x_k<<<dim3(1600, 5, 5), dim3(32, 8)>>>(x);
    conv_k<159, 150, 15><<<NB * NW, 256, (100 * 159 + 64) * 4>>>((const float*)pxT, (const float*)pw1, bc1, (float*)pc1);
    conv_k<150, 141, 15><<<NB * NW, 256, (100 * 150 + 64) * 4>>>((const float*)pc1, (const float*)pw2, bc2, (float*)pc2);
    conv_k<141, 132, 14><<<NB * NW, 256, (100 * 141 + 64) * 4>>>((const float*)pc2, (const float*)pw3, bc3, (float*)pc3);
    transpose_c_k<<<dim3(1600, 5, 5), dim3(32, 8)>>>();
    gemm_xw_k<<<dim3(25, 5), 256>>>(w_ih);
    gru_k<<<16, 320>>>(w_hh, b_ih, b_hh);
    heads_k<<<(1600 * 17 + 255) / 256, 256>>>(w_y1, b_y1, w_y2, b_y2, out);
}